// round 12
// baseline (speedup 1.0000x reference)
#include <cuda_runtime.h>
#include <cuda_fp16.h>

// CSWin attention: B=2, H=64, W=64, N=4, DIM=128, HEADS=4, SPLIT=2
// 64 windows, L=512 tokens/window, head_dim=32, 4 heads.
// Token t: hh = t>>3, ww = (t>>2)&1, nn = t&3 ; spatial group sp = t>>2.
// Grid: 512 CTAs = (window, head, row-half). 256 threads = 8 warps x 32 rows.

#define FULLMASK 0xffffffffu
#define KST2 18       // u32 stride of Ku rows: banks (18g+t)%32 all distinct
#define VTSTR 260     // u32 stride of VT rows: banks 4g+t -> conflict-free
#define VSUMSTR 33

__device__ __forceinline__ int goff(int b, int hh, int wd, int nn, int c) {
    return (((b * 64 + hh) * 64 + wd) * 4 + nn) * 128 + c;
}

__device__ __forceinline__ unsigned h2u(__half2 h) {
    return *reinterpret_cast<unsigned*>(&h);
}
__device__ __forceinline__ __half2 uh2(unsigned u) {
    return *reinterpret_cast<__half2*>(&u);
}

// packed half2 exp2
__device__ __forceinline__ unsigned h2ex2(unsigned x) {
    unsigned r;
    asm("ex2.approx.f16x2 %0, %1;" : "=r"(r) : "r"(x));
    return r;
}

// D += A(16x16,f16) * B(16x8,f16), row.col, f32 accum
__device__ __forceinline__ void mma_f16(float c[4], unsigned a0, unsigned a1,
                                        unsigned a2, unsigned a3,
                                        unsigned b0, unsigned b1) {
    asm volatile(
        "mma.sync.aligned.m16n8k16.row.col.f32.f16.f16.f32 "
        "{%0,%1,%2,%3}, {%4,%5,%6,%7}, {%8,%9}, {%0,%1,%2,%3};\n"
        : "+f"(c[0]), "+f"(c[1]), "+f"(c[2]), "+f"(c[3])
        : "r"(a0), "r"(a1), "r"(a2), "r"(a3), "r"(b0), "r"(b1));
}

// ---------------------------------------------------------------------------
// Fused flash attention + RPE, all-fp16 MMA. One CTA per (window, head, half):
// 8 warps, each owns 32 rows (two m16 tiles). Full window K/V staged in smem
// (each window staged by 2 CTAs -- gmem is cheap, occupancy is not).
// smem: Ku[512][18] u32 + VT[32][260] u32 + CW[288]. 3 CTAs/SM via
// __launch_bounds__(256,3) -> 24 warps/SM for latency hiding.
// ---------------------------------------------------------------------------
__global__ __launch_bounds__(256, 3)
void cswin_fused(const float* __restrict__ q, const float* __restrict__ k,
                 const float* __restrict__ v, const float* __restrict__ cw,
                 float* __restrict__ out)
{
    extern __shared__ unsigned smu[];
    unsigned* Ku  = smu;                          // 512*18 u32
    unsigned* VTu = smu + 512 * KST2;             // 32*260 u32
    __half*   VT16 = (__half*)VTu;                // [32][520] halves
    float*    CWs = (float*)(smu + 512 * KST2 + 32 * VTSTR); // 288 floats
    float*    Vsum = (float*)Ku;                  // reused after main loop

    const float NEG_INF = __int_as_float(0xff800000);
    const float SCL = 0.25500766198160955f; // (1/sqrt(32)) * log2(e)

    int bx = blockIdx.x;
    int half_id = bx & 1, h = (bx >> 1) & 3, win = bx >> 3;
    int b = win >> 5, jw = win & 31;
    int cbase = h * 32;
    int tid = threadIdx.x, warp = tid >> 5, lane = tid & 31;
    int g = lane >> 2, t = lane & 3;

    // ---- conv weight slice for this head ----
    if (tid < 144) {
        CWs[tid] = cw[cbase * 9 + tid];
        CWs[tid + 144] = cw[cbase * 9 + tid + 144];
    }

    // ---- stage K (fp16 pairs) and V (fp16 transposed): 2 tokens per thread ----
    #pragma unroll
    for (int tk = 0; tk < 2; tk++) {
        int tok = tid + tk * 256;
        int hh = tok >> 3, ww = (tok >> 2) & 1, nn = tok & 3;
        int ga = goff(b, hh, jw * 2 + ww, nn, cbase);
        unsigned* kd = Ku + tok * KST2;
        #pragma unroll
        for (int cc8 = 0; cc8 < 4; cc8++) {
            float4 k0 = *(const float4*)(k + ga + cc8 * 8);
            float4 k1 = *(const float4*)(k + ga + cc8 * 8 + 4);
            kd[cc8 * 4 + 0] = h2u(__floats2half2_rn(k0.x, k0.y));
            kd[cc8 * 4 + 1] = h2u(__floats2half2_rn(k0.z, k0.w));
            kd[cc8 * 4 + 2] = h2u(__floats2half2_rn(k1.x, k1.y));
            kd[cc8 * 4 + 3] = h2u(__floats2half2_rn(k1.z, k1.w));
            float4 v0 = *(const float4*)(v + ga + cc8 * 8);
            float4 v1 = *(const float4*)(v + ga + cc8 * 8 + 4);
            VT16[(cc8 * 8 + 0) * 520 + tok] = __float2half(v0.x);
            VT16[(cc8 * 8 + 1) * 520 + tok] = __float2half(v0.y);
            VT16[(cc8 * 8 + 2) * 520 + tok] = __float2half(v0.z);
            VT16[(cc8 * 8 + 3) * 520 + tok] = __float2half(v0.w);
            VT16[(cc8 * 8 + 4) * 520 + tok] = __float2half(v1.x);
            VT16[(cc8 * 8 + 5) * 520 + tok] = __float2half(v1.y);
            VT16[(cc8 * 8 + 6) * 520 + tok] = __float2half(v1.z);
            VT16[(cc8 * 8 + 7) * 520 + tok] = __float2half(v1.w);
        }
    }
    __syncthreads();

    // ---- Q fragments straight from gmem (fp16, scale+log2e folded in) ----
    int r0 = half_id * 256 + warp * 32;
    unsigned qf[2][2][4];   // [mt][ks][a-reg]
    #pragma unroll
    for (int mt = 0; mt < 2; mt++)
        #pragma unroll
        for (int ks = 0; ks < 2; ks++)
            #pragma unroll
            for (int rr = 0; rr < 2; rr++) {
                int row = r0 + mt * 16 + g + rr * 8;
                int ga = goff(b, row >> 3, jw * 2 + ((row >> 2) & 1), row & 3,
                              cbase + 16 * ks + 2 * t);
                float2 lo = *(const float2*)(q + ga);
                float2 hi = *(const float2*)(q + ga + 8);
                qf[mt][ks][rr]     = h2u(__floats2half2_rn(lo.x * SCL, lo.y * SCL));
                qf[mt][ks][rr + 2] = h2u(__floats2half2_rn(hi.x * SCL, hi.y * SCL));
            }

    // constant ones B-fragment for row sums (d-column 0 only)
    unsigned ones_b = (g == 0) ? 0x3C003C00u : 0u;

    float O[2][4][4];
    float Osum[2][4];
    #pragma unroll
    for (int mt = 0; mt < 2; mt++) {
        #pragma unroll
        for (int nt = 0; nt < 4; nt++)
            #pragma unroll
            for (int r = 0; r < 4; r++) O[mt][nt][r] = 0.f;
        #pragma unroll
        for (int r = 0; r < 4; r++) Osum[mt][r] = 0.f;
    }

    int diag_c = r0 >> 5;   // chunk containing this warp's diagonal

    #pragma unroll 1
    for (int c = 0; c < 16; c++) {
        int j0 = c * 32;
        bool diag = (c == diag_c);
        unsigned ph[2][4][2];

        // S tiles: compute, mask, exp2(f16x2), pack -- S stays transient per nt.
        #pragma unroll
        for (int nt = 0; nt < 4; nt++) {
            float S0[4] = {0.f, 0.f, 0.f, 0.f};
            float S1[4] = {0.f, 0.f, 0.f, 0.f};
            #pragma unroll
            for (int ks = 0; ks < 2; ks++) {
                const unsigned* kp = Ku + (j0 + nt * 8 + g) * KST2 + ks * 8 + t;
                unsigned b0 = kp[0], b1 = kp[4];
                mma_f16(S0, qf[0][ks][0], qf[0][ks][1], qf[0][ks][2], qf[0][ks][3], b0, b1);
                mma_f16(S1, qf[1][ks][0], qf[1][ks][1], qf[1][ks][2], qf[1][ks][3], b0, b1);
            }
            if (diag) {
                #pragma unroll
                for (int r = 0; r < 4; r++) {
                    int j = j0 + nt * 8 + 2 * t + (r & 1);
                    int i0 = r0 + g + ((r >> 1) ? 8 : 0);
                    int i1 = i0 + 16;
                    if (((i0 >> 2) == (j >> 2)) && (i0 != j)) S0[r] = NEG_INF;
                    if (((i1 >> 2) == (j >> 2)) && (i1 != j)) S1[r] = NEG_INF;
                }
            }
            ph[0][nt][0] = h2ex2(h2u(__floats2half2_rn(S0[0], S0[1])));
            ph[0][nt][1] = h2ex2(h2u(__floats2half2_rn(S0[2], S0[3])));
            ph[1][nt][0] = h2ex2(h2u(__floats2half2_rn(S1[0], S1[1])));
            ph[1][nt][1] = h2ex2(h2u(__floats2half2_rn(S1[2], S1[3])));
        }

        // O += P * V ; row sums via constant ones fragment
        #pragma unroll
        for (int kc = 0; kc < 2; kc++) {
            int vb = (j0 >> 1) + kc * 8 + t;
            #pragma unroll
            for (int vt = 0; vt < 4; vt++) {
                const unsigned* vp = VTu + (vt * 8 + g) * VTSTR + vb;
                unsigned b0 = vp[0], b1 = vp[4];
                mma_f16(O[0][vt], ph[0][2 * kc][0], ph[0][2 * kc][1],
                                  ph[0][2 * kc + 1][0], ph[0][2 * kc + 1][1], b0, b1);
                mma_f16(O[1][vt], ph[1][2 * kc][0], ph[1][2 * kc][1],
                                  ph[1][2 * kc + 1][0], ph[1][2 * kc + 1][1], b0, b1);
            }
            mma_f16(Osum[0], ph[0][2 * kc][0], ph[0][2 * kc][1],
                             ph[0][2 * kc + 1][0], ph[0][2 * kc + 1][1], ones_b, ones_b);
            mma_f16(Osum[1], ph[1][2 * kc][0], ph[1][2 * kc][1],
                             ph[1][2 * kc + 1][0], ph[1][2 * kc + 1][1], ones_b, ones_b);
        }
    }

    // ---- row sums sit in Osum (col 0 -> t==0 lanes, c0/c2) ----
    float inv[4];
    #pragma unroll
    for (int mt = 0; mt < 2; mt++) {
        float l0 = __shfl_sync(FULLMASK, Osum[mt][0], lane & ~3);
        float l1 = __shfl_sync(FULLMASK, Osum[mt][2], lane & ~3);
        inv[mt * 2 + 0] = 1.0f / l0;
        inv[mt * 2 + 1] = 1.0f / l1;
    }

    // ---- build Vsum[sp][c] in the freed K region ----
    __syncthreads();
    for (int e = tid; e < 4096; e += 256) {
        int sp = e >> 5, cc = e & 31;
        unsigned u0 = VTu[cc * VTSTR + sp * 2];
        unsigned u1 = VTu[cc * VTSTR + sp * 2 + 1];
        float2 f0 = __half22float2(uh2(u0));
        float2 f1 = __half22float2(uh2(u1));
        Vsum[sp * VSUMSTR + cc] = f0.x + f0.y + f1.x + f1.y;
    }
    __syncthreads();

    // ---- epilogue: out = O/l + rpe ----
    #pragma unroll
    for (int mt = 0; mt < 2; mt++)
        #pragma unroll
        for (int nt = 0; nt < 4; nt++) {
            int c0 = nt * 8 + 2 * t;   // channel within head
            #pragma unroll
            for (int half = 0; half < 2; half++) {
                int i = r0 + mt * 16 + g + half * 8;
                int sp = i >> 2;
                int hh = sp >> 1, ww = sp & 1;
                float2 val;
                val.x = O[mt][nt][half * 2 + 0] * inv[mt * 2 + half];
                val.y = O[mt][nt][half * 2 + 1] * inv[mt * 2 + half];
                #pragma unroll
                for (int cc = 0; cc < 2; cc++) {
                    int ch = c0 + cc;
                    const float* wc = CWs + ch * 9;
                    float acc = 0.f;
                    #pragma unroll
                    for (int ky = 0; ky < 3; ky++) {
                        int h2 = hh + ky - 1;
                        if (h2 < 0 || h2 >= 64) continue;
                        #pragma unroll
                        for (int kx = 0; kx < 3; kx++) {
                            int w2 = ww + kx - 1;
                            if (w2 < 0 || w2 >= 2) continue;
                            acc += wc[ky * 3 + kx] * Vsum[(h2 * 2 + w2) * VSUMSTR + ch];
                        }
                    }
                    float center = wc[4];
                    float vi = __half2float(VT16[ch * 520 + i]);
                    float rpe = acc - center * (Vsum[sp * VSUMSTR + ch] - vi);
                    if (cc == 0) val.x += rpe; else val.y += rpe;
                }
                int ga = goff(b, i >> 3, jw * 2 + ((i >> 2) & 1), i & 3, cbase + c0);
                *(float2*)(out + ga) = val;
            }
        }
}

extern "C" void kernel_launch(void* const* d_in, const int* in_sizes, int n_in,
                              void* d_out, int out_size)
{
    const float* q  = (const float*)d_in[0];
    const float* k  = (const float*)d_in[1];
    const float* v  = (const float*)d_in[2];
    const float* cw = (const float*)d_in[3];
    float* out = (float*)d_out;

    const int SMEM = (512 * KST2 + 32 * VTSTR + 288) * 4;  // 71296 B

    cudaFuncSetAttribute(cswin_fused,
                         cudaFuncAttributeMaxDynamicSharedMemorySize, SMEM);
    cswin_fused<<<512, 256, SMEM>>>(q, k, v, cw, out);
}

// round 13
// speedup vs baseline: 1.5554x; 1.5554x over previous
#include <cuda_runtime.h>
#include <cuda_fp16.h>

// CSWin attention: B=2, H=64, W=64, N=4, DIM=128, HEADS=4, SPLIT=2
// 64 windows, L=512 tokens/window, head_dim=32, 4 heads.
// Token t: hh = t>>3, ww = (t>>2)&1, nn = t&3 ; spatial group sp = t>>2.

#define FULLMASK 0xffffffffu
#define KST2 20       // u32 stride of Ku rows: banks 20g+t -> conflict-free
#define VTSTR 260     // u32 stride of VT rows: banks 4g+t -> conflict-free
#define VSUMSTR 33

__device__ __forceinline__ int goff(int b, int hh, int wd, int nn, int c) {
    return (((b * 64 + hh) * 64 + wd) * 4 + nn) * 128 + c;
}

__device__ __forceinline__ unsigned h2u(__half2 h) {
    return *reinterpret_cast<unsigned*>(&h);
}
__device__ __forceinline__ __half2 uh2(unsigned u) {
    return *reinterpret_cast<__half2*>(&u);
}

// packed half2 exp2
__device__ __forceinline__ unsigned h2ex2(unsigned x) {
    unsigned r;
    asm("ex2.approx.f16x2 %0, %1;" : "=r"(r) : "r"(x));
    return r;
}

// D += A(16x16,f16) * B(16x8,f16), row.col, f32 accum
__device__ __forceinline__ void mma_f16(float c[4], unsigned a0, unsigned a1,
                                        unsigned a2, unsigned a3,
                                        unsigned b0, unsigned b1) {
    asm volatile(
        "mma.sync.aligned.m16n8k16.row.col.f32.f16.f16.f32 "
        "{%0,%1,%2,%3}, {%4,%5,%6,%7}, {%8,%9}, {%0,%1,%2,%3};\n"
        : "+f"(c[0]), "+f"(c[1]), "+f"(c[2]), "+f"(c[3])
        : "r"(a0), "r"(a1), "r"(a2), "r"(a3), "r"(b0), "r"(b1));
}

// ---------------------------------------------------------------------------
// Fused flash attention + RPE, all-fp16 MMA. One CTA per (window, head),
// 512 threads = 16 warps, 32 rows per warp (two m16 tiles -> B-frag reuse).
// smem: Ku[512][20] u32 (K fp16 channel-pairs per token)
//     + VT[32][260] u32 (V fp16 token-pairs per channel) + CW[288].
// Q fragments load straight from gmem. P stays in registers: QK C-fragments
// repack directly into fp16 A-fragments for PV. Row sums via MMA against a
// constant ones B-fragment. Ku region is reused for Vsum in the epilogue.
// Chunk loop unrolled x2 so ptxas can software-pipeline PV(c) with QK(c+1).
// ---------------------------------------------------------------------------
__global__ __launch_bounds__(512, 1)
void cswin_fused(const float* __restrict__ q, const float* __restrict__ k,
                 const float* __restrict__ v, const float* __restrict__ cw,
                 float* __restrict__ out)
{
    extern __shared__ unsigned smu[];
    unsigned* Ku  = smu;                          // 512*20 u32
    unsigned* VTu = smu + 512 * KST2;             // 32*260 u32
    __half*   VT16 = (__half*)VTu;                // [32][520] halves
    float*    CWs = (float*)(smu + 512 * KST2 + 32 * VTSTR); // 288 floats
    float*    Vsum = (float*)Ku;                  // reused after main loop

    const float NEG_INF = __int_as_float(0xff800000);
    const float SCL = 0.25500766198160955f; // (1/sqrt(32)) * log2(e)

    int bx = blockIdx.x;
    int win = bx >> 2, h = bx & 3;
    int b = win >> 5, jw = win & 31;
    int cbase = h * 32;
    int tid = threadIdx.x, warp = tid >> 5, lane = tid & 31;
    int g = lane >> 2, t = lane & 3;

    // ---- conv weight slice for this head ----
    if (tid < 288) CWs[tid] = cw[cbase * 9 + tid];

    // ---- stage K (fp16 pairs) and V (fp16 transposed): 1 thread per token ----
    {
        int tok = tid;
        int hh = tok >> 3, ww = (tok >> 2) & 1, nn = tok & 3;
        int ga = goff(b, hh, jw * 2 + ww, nn, cbase);
        unsigned* kd = Ku + tok * KST2;
        #pragma unroll
        for (int cc8 = 0; cc8 < 4; cc8++) {
            float4 k0 = *(const float4*)(k + ga + cc8 * 8);
            float4 k1 = *(const float4*)(k + ga + cc8 * 8 + 4);
            kd[cc8 * 4 + 0] = h2u(__floats2half2_rn(k0.x, k0.y));
            kd[cc8 * 4 + 1] = h2u(__floats2half2_rn(k0.z, k0.w));
            kd[cc8 * 4 + 2] = h2u(__floats2half2_rn(k1.x, k1.y));
            kd[cc8 * 4 + 3] = h2u(__floats2half2_rn(k1.z, k1.w));
            float4 v0 = *(const float4*)(v + ga + cc8 * 8);
            float4 v1 = *(const float4*)(v + ga + cc8 * 8 + 4);
            VT16[(cc8 * 8 + 0) * 520 + tok] = __float2half(v0.x);
            VT16[(cc8 * 8 + 1) * 520 + tok] = __float2half(v0.y);
            VT16[(cc8 * 8 + 2) * 520 + tok] = __float2half(v0.z);
            VT16[(cc8 * 8 + 3) * 520 + tok] = __float2half(v0.w);
            VT16[(cc8 * 8 + 4) * 520 + tok] = __float2half(v1.x);
            VT16[(cc8 * 8 + 5) * 520 + tok] = __float2half(v1.y);
            VT16[(cc8 * 8 + 6) * 520 + tok] = __float2half(v1.z);
            VT16[(cc8 * 8 + 7) * 520 + tok] = __float2half(v1.w);
        }
    }
    __syncthreads();

    // ---- Q fragments straight from gmem (fp16, scale+log2e folded in) ----
    int r0 = warp * 32;
    unsigned qf[2][2][4];   // [mt][ks][a-reg]
    #pragma unroll
    for (int mt = 0; mt < 2; mt++)
        #pragma unroll
        for (int ks = 0; ks < 2; ks++)
            #pragma unroll
            for (int rr = 0; rr < 2; rr++) {
                int row = r0 + mt * 16 + g + rr * 8;
                int ga = goff(b, row >> 3, jw * 2 + ((row >> 2) & 1), row & 3,
                              cbase + 16 * ks + 2 * t);
                float2 lo = *(const float2*)(q + ga);
                float2 hi = *(const float2*)(q + ga + 8);
                qf[mt][ks][rr]     = h2u(__floats2half2_rn(lo.x * SCL, lo.y * SCL));
                qf[mt][ks][rr + 2] = h2u(__floats2half2_rn(hi.x * SCL, hi.y * SCL));
            }

    // constant ones B-fragment for row sums (d-column 0 only)
    unsigned ones_b = (g == 0) ? 0x3C003C00u : 0u;

    float O[2][4][4];
    float Osum[2][4];
    #pragma unroll
    for (int mt = 0; mt < 2; mt++) {
        #pragma unroll
        for (int nt = 0; nt < 4; nt++)
            #pragma unroll
            for (int r = 0; r < 4; r++) O[mt][nt][r] = 0.f;
        #pragma unroll
        for (int r = 0; r < 4; r++) Osum[mt][r] = 0.f;
    }

    #pragma unroll 2
    for (int c = 0; c < 16; c++) {
        int j0 = c * 32;
        bool diag = (c == warp);
        unsigned ph[2][4][2];

        // S tiles: compute, mask, exp2(f16x2), pack -- S stays transient per nt.
        #pragma unroll
        for (int nt = 0; nt < 4; nt++) {
            float S0[4] = {0.f, 0.f, 0.f, 0.f};
            float S1[4] = {0.f, 0.f, 0.f, 0.f};
            #pragma unroll
            for (int ks = 0; ks < 2; ks++) {
                const unsigned* kp = Ku + (j0 + nt * 8 + g) * KST2 + ks * 8 + t;
                unsigned b0 = kp[0], b1 = kp[4];
                mma_f16(S0, qf[0][ks][0], qf[0][ks][1], qf[0][ks][2], qf[0][ks][3], b0, b1);
                mma_f16(S1, qf[1][ks][0], qf[1][ks][1], qf[1][ks][2], qf[1][ks][3], b0, b1);
            }
            if (diag) {
                #pragma unroll
                for (int r = 0; r < 4; r++) {
                    int j = j0 + nt * 8 + 2 * t + (r & 1);
                    int i0 = r0 + g + ((r >> 1) ? 8 : 0);
                    int i1 = i0 + 16;
                    if (((i0 >> 2) == (j >> 2)) && (i0 != j)) S0[r] = NEG_INF;
                    if (((i1 >> 2) == (j >> 2)) && (i1 != j)) S1[r] = NEG_INF;
                }
            }
            ph[0][nt][0] = h2ex2(h2u(__floats2half2_rn(S0[0], S0[1])));
            ph[0][nt][1] = h2ex2(h2u(__floats2half2_rn(S0[2], S0[3])));
            ph[1][nt][0] = h2ex2(h2u(__floats2half2_rn(S1[0], S1[1])));
            ph[1][nt][1] = h2ex2(h2u(__floats2half2_rn(S1[2], S1[3])));
        }

        // O += P * V ; row sums via constant ones fragment
        #pragma unroll
        for (int kc = 0; kc < 2; kc++) {
            int vb = (j0 >> 1) + kc * 8 + t;
            #pragma unroll
            for (int vt = 0; vt < 4; vt++) {
                const unsigned* vp = VTu + (vt * 8 + g) * VTSTR + vb;
                unsigned b0 = vp[0], b1 = vp[4];
                mma_f16(O[0][vt], ph[0][2 * kc][0], ph[0][2 * kc][1],
                                  ph[0][2 * kc + 1][0], ph[0][2 * kc + 1][1], b0, b1);
                mma_f16(O[1][vt], ph[1][2 * kc][0], ph[1][2 * kc][1],
                                  ph[1][2 * kc + 1][0], ph[1][2 * kc + 1][1], b0, b1);
            }
            mma_f16(Osum[0], ph[0][2 * kc][0], ph[0][2 * kc][1],
                             ph[0][2 * kc + 1][0], ph[0][2 * kc + 1][1], ones_b, ones_b);
            mma_f16(Osum[1], ph[1][2 * kc][0], ph[1][2 * kc][1],
                             ph[1][2 * kc + 1][0], ph[1][2 * kc + 1][1], ones_b, ones_b);
        }
    }

    // ---- row sums sit in Osum (col 0 -> t==0 lanes, c0/c2) ----
    float inv[4];
    #pragma unroll
    for (int mt = 0; mt < 2; mt++) {
        float l0 = __shfl_sync(FULLMASK, Osum[mt][0], lane & ~3);
        float l1 = __shfl_sync(FULLMASK, Osum[mt][2], lane & ~3);
        inv[mt * 2 + 0] = 1.0f / l0;
        inv[mt * 2 + 1] = 1.0f / l1;
    }

    // ---- build Vsum[sp][c] in the freed K region ----
    __syncthreads();
    for (int e = tid; e < 4096; e += 512) {
        int sp = e >> 5, cc = e & 31;
        unsigned u0 = VTu[cc * VTSTR + sp * 2];
        unsigned u1 = VTu[cc * VTSTR + sp * 2 + 1];
        float2 f0 = __half22float2(uh2(u0));
        float2 f1 = __half22float2(uh2(u1));
        Vsum[sp * VSUMSTR + cc] = f0.x + f0.y + f1.x + f1.y;
    }
    __syncthreads();

    // ---- epilogue: out = O/l + rpe ----
    #pragma unroll
    for (int mt = 0; mt < 2; mt++)
        #pragma unroll
        for (int nt = 0; nt < 4; nt++) {
            int c0 = nt * 8 + 2 * t;   // channel within head
            #pragma unroll
            for (int half = 0; half < 2; half++) {
                int i = r0 + mt * 16 + g + half * 8;
                int sp = i >> 2;
                int hh = sp >> 1, ww = sp & 1;
                float2 val;
                val.x = O[mt][nt][half * 2 + 0] * inv[mt * 2 + half];
                val.y = O[mt][nt][half * 2 + 1] * inv[mt * 2 + half];
                #pragma unroll
                for (int cc = 0; cc < 2; cc++) {
                    int ch = c0 + cc;
                    const float* wc = CWs + ch * 9;
                    float acc = 0.f;
                    #pragma unroll
                    for (int ky = 0; ky < 3; ky++) {
                        int h2 = hh + ky - 1;
                        if (h2 < 0 || h2 >= 64) continue;
                        #pragma unroll
                        for (int kx = 0; kx < 3; kx++) {
                            int w2 = ww + kx - 1;
                            if (w2 < 0 || w2 >= 2) continue;
                            acc += wc[ky * 3 + kx] * Vsum[(h2 * 2 + w2) * VSUMSTR + ch];
                        }
                    }
                    float center = wc[4];
                    float vi = __half2float(VT16[ch * 520 + i]);
                    float rpe = acc - center * (Vsum[sp * VSUMSTR + ch] - vi);
                    if (cc == 0) val.x += rpe; else val.y += rpe;
                }
                int ga = goff(b, i >> 3, jw * 2 + ((i >> 2) & 1), i & 3, cbase + c0);
                *(float2*)(out + ga) = val;
            }
        }
}

extern "C" void kernel_launch(void* const* d_in, const int* in_sizes, int n_in,
                              void* d_out, int out_size)
{
    const float* q  = (const float*)d_in[0];
    const float* k  = (const float*)d_in[1];
    const float* v  = (const float*)d_in[2];
    const float* cw = (const float*)d_in[3];
    float* out = (float*)d_out;

    const int SMEM = (512 * KST2 + 32 * VTSTR + 288) * 4;  // 75392 B

    cudaFuncSetAttribute(cswin_fused,
                         cudaFuncAttributeMaxDynamicSharedMemorySize, SMEM);
    cswin_fused<<<256, 512, SMEM>>>(q, k, v, cw, out);
}

// round 14
// speedup vs baseline: 1.6893x; 1.0861x over previous
#include <cuda_runtime.h>
#include <cuda_fp16.h>

// CSWin attention: B=2, H=64, W=64, N=4, DIM=128, HEADS=4, SPLIT=2
// 64 windows, L=512 tokens/window, head_dim=32, 4 heads.
// Token t: hh = t>>3, ww = (t>>2)&1, nn = t&3 ; spatial group sp = t>>2.

#define FULLMASK 0xffffffffu
#define KST2 20       // u32 stride of Ku rows: banks 20g+t -> conflict-free
#define VTSTR 260     // u32 stride of VT rows: banks 4g+t -> conflict-free
#define VSUMSTR 33

__device__ __forceinline__ int goff(int b, int hh, int wd, int nn, int c) {
    return (((b * 64 + hh) * 64 + wd) * 4 + nn) * 128 + c;
}

__device__ __forceinline__ unsigned h2u(__half2 h) {
    return *reinterpret_cast<unsigned*>(&h);
}
__device__ __forceinline__ __half2 uh2(unsigned u) {
    return *reinterpret_cast<__half2*>(&u);
}

// packed half2 exp2
__device__ __forceinline__ unsigned h2ex2(unsigned x) {
    unsigned r;
    asm("ex2.approx.f16x2 %0, %1;" : "=r"(r) : "r"(x));
    return r;
}

// D += A(16x16,f16) * B(16x8,f16), row.col, f32 accum
__device__ __forceinline__ void mma_f16(float c[4], unsigned a0, unsigned a1,
                                        unsigned a2, unsigned a3,
                                        unsigned b0, unsigned b1) {
    asm volatile(
        "mma.sync.aligned.m16n8k16.row.col.f32.f16.f16.f32 "
        "{%0,%1,%2,%3}, {%4,%5,%6,%7}, {%8,%9}, {%0,%1,%2,%3};\n"
        : "+f"(c[0]), "+f"(c[1]), "+f"(c[2]), "+f"(c[3])
        : "r"(a0), "r"(a1), "r"(a2), "r"(a3), "r"(b0), "r"(b1));
}

// ---------------------------------------------------------------------------
// Fused flash attention + RPE, all-fp16 MMA. One CTA per (window, head),
// 512 threads = 16 warps, 32 rows per warp (two m16 tiles -> B-frag reuse).
// smem: Ku[512][20] u32 + VT[32][260] u32 + CW[288].
// Q fragments load straight from gmem. P stays in registers. Row sums via
// a constant ones B-fragment. Chunk loop unrolled x2 (software pipelining).
// Epilogue: rpe(i,c) = R(sp,c) + center_c*v(i,c), with R = conv(Vsum) -
// center*Vsum precomputed cooperatively in the freed Ku region.
// ---------------------------------------------------------------------------
__global__ __launch_bounds__(512, 1)
void cswin_fused(const float* __restrict__ q, const float* __restrict__ k,
                 const float* __restrict__ v, const float* __restrict__ cw,
                 float* __restrict__ out)
{
    extern __shared__ unsigned smu[];
    unsigned* Ku  = smu;                          // 512*20 u32
    unsigned* VTu = smu + 512 * KST2;             // 32*260 u32
    __half*   VT16 = (__half*)VTu;                // [32][520] halves
    float*    CWs = (float*)(smu + 512 * KST2 + 32 * VTSTR); // 288 floats

    const float NEG_INF = __int_as_float(0xff800000);
    const float SCL = 0.25500766198160955f; // (1/sqrt(32)) * log2(e)

    int bx = blockIdx.x;
    int win = bx >> 2, h = bx & 3;
    int b = win >> 5, jw = win & 31;
    int cbase = h * 32;
    int tid = threadIdx.x, warp = tid >> 5, lane = tid & 31;
    int g = lane >> 2, t = lane & 3;

    // ---- conv weight slice for this head ----
    if (tid < 288) CWs[tid] = cw[cbase * 9 + tid];

    // ---- stage K (fp16 pairs) and V (fp16 transposed, u32 pair writes) ----
    // thread = (token-pair p, channel-half): handles tokens 2p,2p+1,
    // channels [ch0, ch0+16).
    {
        int p = tid & 255, ch0 = (tid >> 8) * 16;
        int tok0 = 2 * p;
        int hh = tok0 >> 3, ww = (tok0 >> 2) & 1, nn0 = tok0 & 3;
        int ga0 = goff(b, hh, jw * 2 + ww, nn0, cbase + ch0);
        int ga1 = ga0 + 128;   // token 2p+1: nn+1 -> +128 floats

        float4 ka0 = *(const float4*)(k + ga0);
        float4 ka1 = *(const float4*)(k + ga0 + 4);
        float4 ka2 = *(const float4*)(k + ga0 + 8);
        float4 ka3 = *(const float4*)(k + ga0 + 12);
        unsigned* kd0 = Ku + tok0 * KST2 + ch0 / 2;
        kd0[0] = h2u(__floats2half2_rn(ka0.x, ka0.y));
        kd0[1] = h2u(__floats2half2_rn(ka0.z, ka0.w));
        kd0[2] = h2u(__floats2half2_rn(ka1.x, ka1.y));
        kd0[3] = h2u(__floats2half2_rn(ka1.z, ka1.w));
        kd0[4] = h2u(__floats2half2_rn(ka2.x, ka2.y));
        kd0[5] = h2u(__floats2half2_rn(ka2.z, ka2.w));
        kd0[6] = h2u(__floats2half2_rn(ka3.x, ka3.y));
        kd0[7] = h2u(__floats2half2_rn(ka3.z, ka3.w));
        float4 kb0 = *(const float4*)(k + ga1);
        float4 kb1 = *(const float4*)(k + ga1 + 4);
        float4 kb2 = *(const float4*)(k + ga1 + 8);
        float4 kb3 = *(const float4*)(k + ga1 + 12);
        unsigned* kd1 = kd0 + KST2;
        kd1[0] = h2u(__floats2half2_rn(kb0.x, kb0.y));
        kd1[1] = h2u(__floats2half2_rn(kb0.z, kb0.w));
        kd1[2] = h2u(__floats2half2_rn(kb1.x, kb1.y));
        kd1[3] = h2u(__floats2half2_rn(kb1.z, kb1.w));
        kd1[4] = h2u(__floats2half2_rn(kb2.x, kb2.y));
        kd1[5] = h2u(__floats2half2_rn(kb2.z, kb2.w));
        kd1[6] = h2u(__floats2half2_rn(kb3.x, kb3.y));
        kd1[7] = h2u(__floats2half2_rn(kb3.z, kb3.w));

        float4 va0 = *(const float4*)(v + ga0);
        float4 va1 = *(const float4*)(v + ga0 + 4);
        float4 va2 = *(const float4*)(v + ga0 + 8);
        float4 va3 = *(const float4*)(v + ga0 + 12);
        float4 vb0 = *(const float4*)(v + ga1);
        float4 vb1 = *(const float4*)(v + ga1 + 4);
        float4 vb2 = *(const float4*)(v + ga1 + 8);
        float4 vb3 = *(const float4*)(v + ga1 + 12);
        unsigned* vd = VTu + ch0 * VTSTR + p;
        vd[0 * VTSTR]  = h2u(__floats2half2_rn(va0.x, vb0.x));
        vd[1 * VTSTR]  = h2u(__floats2half2_rn(va0.y, vb0.y));
        vd[2 * VTSTR]  = h2u(__floats2half2_rn(va0.z, vb0.z));
        vd[3 * VTSTR]  = h2u(__floats2half2_rn(va0.w, vb0.w));
        vd[4 * VTSTR]  = h2u(__floats2half2_rn(va1.x, vb1.x));
        vd[5 * VTSTR]  = h2u(__floats2half2_rn(va1.y, vb1.y));
        vd[6 * VTSTR]  = h2u(__floats2half2_rn(va1.z, vb1.z));
        vd[7 * VTSTR]  = h2u(__floats2half2_rn(va1.w, vb1.w));
        vd[8 * VTSTR]  = h2u(__floats2half2_rn(va2.x, vb2.x));
        vd[9 * VTSTR]  = h2u(__floats2half2_rn(va2.y, vb2.y));
        vd[10 * VTSTR] = h2u(__floats2half2_rn(va2.z, vb2.z));
        vd[11 * VTSTR] = h2u(__floats2half2_rn(va2.w, vb2.w));
        vd[12 * VTSTR] = h2u(__floats2half2_rn(va3.x, vb3.x));
        vd[13 * VTSTR] = h2u(__floats2half2_rn(va3.y, vb3.y));
        vd[14 * VTSTR] = h2u(__floats2half2_rn(va3.z, vb3.z));
        vd[15 * VTSTR] = h2u(__floats2half2_rn(va3.w, vb3.w));
    }
    __syncthreads();

    // ---- Q fragments straight from gmem (fp16, scale+log2e folded in) ----
    int r0 = warp * 32;
    unsigned qf[2][2][4];   // [mt][ks][a-reg]
    #pragma unroll
    for (int mt = 0; mt < 2; mt++)
        #pragma unroll
        for (int ks = 0; ks < 2; ks++)
            #pragma unroll
            for (int rr = 0; rr < 2; rr++) {
                int row = r0 + mt * 16 + g + rr * 8;
                int ga = goff(b, row >> 3, jw * 2 + ((row >> 2) & 1), row & 3,
                              cbase + 16 * ks + 2 * t);
                float2 lo = *(const float2*)(q + ga);
                float2 hi = *(const float2*)(q + ga + 8);
                qf[mt][ks][rr]     = h2u(__floats2half2_rn(lo.x * SCL, lo.y * SCL));
                qf[mt][ks][rr + 2] = h2u(__floats2half2_rn(hi.x * SCL, hi.y * SCL));
            }

    // constant ones B-fragment for row sums (d-column 0 only)
    unsigned ones_b = (g == 0) ? 0x3C003C00u : 0u;

    float O[2][4][4];
    float Osum[2][4];
    #pragma unroll
    for (int mt = 0; mt < 2; mt++) {
        #pragma unroll
        for (int nt = 0; nt < 4; nt++)
            #pragma unroll
            for (int r = 0; r < 4; r++) O[mt][nt][r] = 0.f;
        #pragma unroll
        for (int r = 0; r < 4; r++) Osum[mt][r] = 0.f;
    }

    #pragma unroll 2
    for (int c = 0; c < 16; c++) {
        int j0 = c * 32;
        bool diag = (c == warp);
        unsigned ph[2][4][2];

        // S tiles: compute, mask, exp2(f16x2), pack -- S stays transient per nt.
        #pragma unroll
        for (int nt = 0; nt < 4; nt++) {
            float S0[4] = {0.f, 0.f, 0.f, 0.f};
            float S1[4] = {0.f, 0.f, 0.f, 0.f};
            #pragma unroll
            for (int ks = 0; ks < 2; ks++) {
                const unsigned* kp = Ku + (j0 + nt * 8 + g) * KST2 + ks * 8 + t;
                unsigned b0 = kp[0], b1 = kp[4];
                mma_f16(S0, qf[0][ks][0], qf[0][ks][1], qf[0][ks][2], qf[0][ks][3], b0, b1);
                mma_f16(S1, qf[1][ks][0], qf[1][ks][1], qf[1][ks][2], qf[1][ks][3], b0, b1);
            }
            if (diag) {
                #pragma unroll
                for (int r = 0; r < 4; r++) {
                    int j = j0 + nt * 8 + 2 * t + (r & 1);
                    int i0 = r0 + g + ((r >> 1) ? 8 : 0);
                    int i1 = i0 + 16;
                    if (((i0 >> 2) == (j >> 2)) && (i0 != j)) S0[r] = NEG_INF;
                    if (((i1 >> 2) == (j >> 2)) && (i1 != j)) S1[r] = NEG_INF;
                }
            }
            ph[0][nt][0] = h2ex2(h2u(__floats2half2_rn(S0[0], S0[1])));
            ph[0][nt][1] = h2ex2(h2u(__floats2half2_rn(S0[2], S0[3])));
            ph[1][nt][0] = h2ex2(h2u(__floats2half2_rn(S1[0], S1[1])));
            ph[1][nt][1] = h2ex2(h2u(__floats2half2_rn(S1[2], S1[3])));
        }

        // O += P * V ; row sums via constant ones fragment
        #pragma unroll
        for (int kc = 0; kc < 2; kc++) {
            int vb = (j0 >> 1) + kc * 8 + t;
            #pragma unroll
            for (int vt = 0; vt < 4; vt++) {
                const unsigned* vp = VTu + (vt * 8 + g) * VTSTR + vb;
                unsigned b0 = vp[0], b1 = vp[4];
                mma_f16(O[0][vt], ph[0][2 * kc][0], ph[0][2 * kc][1],
                                  ph[0][2 * kc + 1][0], ph[0][2 * kc + 1][1], b0, b1);
                mma_f16(O[1][vt], ph[1][2 * kc][0], ph[1][2 * kc][1],
                                  ph[1][2 * kc + 1][0], ph[1][2 * kc + 1][1], b0, b1);
            }
            mma_f16(Osum[0], ph[0][2 * kc][0], ph[0][2 * kc][1],
                             ph[0][2 * kc + 1][0], ph[0][2 * kc + 1][1], ones_b, ones_b);
            mma_f16(Osum[1], ph[1][2 * kc][0], ph[1][2 * kc][1],
                             ph[1][2 * kc + 1][0], ph[1][2 * kc + 1][1], ones_b, ones_b);
        }
    }

    // ---- row sums sit in Osum (col 0 -> t==0 lanes, c0/c2) ----
    float inv[4];
    #pragma unroll
    for (int mt = 0; mt < 2; mt++) {
        float l0 = __shfl_sync(FULLMASK, Osum[mt][0], lane & ~3);
        float l1 = __shfl_sync(FULLMASK, Osum[mt][2], lane & ~3);
        inv[mt * 2 + 0] = 1.0f / l0;
        inv[mt * 2 + 1] = 1.0f / l1;
    }

    // ---- cooperative RPE precompute in the freed K region ----
    float* Vsum = (float*)Ku;          // [128 sp][VSUMSTR]
    float* Rpe  = (float*)Ku + 4224;   // [128 sp][VSUMSTR]
    __syncthreads();
    for (int e = tid; e < 4096; e += 512) {
        int sp = e >> 5, cc = e & 31;
        unsigned u0 = VTu[cc * VTSTR + sp * 2];
        unsigned u1 = VTu[cc * VTSTR + sp * 2 + 1];
        float2 f0 = __half22float2(uh2(u0));
        float2 f1 = __half22float2(uh2(u1));
        Vsum[sp * VSUMSTR + cc] = f0.x + f0.y + f1.x + f1.y;
    }
    __syncthreads();
    for (int e = tid; e < 4096; e += 512) {
        int sp = e >> 5, cc = e & 31;
        int hh = sp >> 1, ww = sp & 1;
        const float* wc = CWs + cc * 9;
        float acc = 0.f;
        #pragma unroll
        for (int ky = 0; ky < 3; ky++) {
            int h2 = hh + ky - 1;
            if (h2 < 0 || h2 >= 64) continue;
            #pragma unroll
            for (int kx = 0; kx < 3; kx++) {
                int w2 = ww + kx - 1;
                if (w2 < 0 || w2 >= 2) continue;
                acc += wc[ky * 3 + kx] * Vsum[(h2 * 2 + w2) * VSUMSTR + cc];
            }
        }
        Rpe[sp * VSUMSTR + cc] = acc - wc[4] * Vsum[sp * VSUMSTR + cc];
    }
    __syncthreads();

    // ---- epilogue: out = O/l + R(sp,c) + center_c*v(i,c) ----
    #pragma unroll
    for (int mt = 0; mt < 2; mt++)
        #pragma unroll
        for (int nt = 0; nt < 4; nt++) {
            int c0 = nt * 8 + 2 * t;   // channel within head
            float ctr0 = CWs[c0 * 9 + 4];
            float ctr1 = CWs[(c0 + 1) * 9 + 4];
            #pragma unroll
            for (int half = 0; half < 2; half++) {
                int i = r0 + mt * 16 + g + half * 8;
                int sp = i >> 2;
                float2 val;
                val.x = O[mt][nt][half * 2 + 0] * inv[mt * 2 + half]
                      + Rpe[sp * VSUMSTR + c0]
                      + ctr0 * __half2float(VT16[c0 * 520 + i]);
                val.y = O[mt][nt][half * 2 + 1] * inv[mt * 2 + half]
                      + Rpe[sp * VSUMSTR + c0 + 1]
                      + ctr1 * __half2float(VT16[(c0 + 1) * 520 + i]);
                int ga = goff(b, i >> 3, jw * 2 + ((i >> 2) & 1), i & 3, cbase + c0);
                *(float2*)(out + ga) = val;
            }
        }
}

extern "C" void kernel_launch(void* const* d_in, const int* in_sizes, int n_in,
                              void* d_out, int out_size)
{
    const float* q  = (const float*)d_in[0];
    const float* k  = (const float*)d_in[1];
    const float* v  = (const float*)d_in[2];
    const float* cw = (const float*)d_in[3];
    float* out = (float*)d_out;

    const int SMEM = (512 * KST2 + 32 * VTSTR + 288) * 4;  // 75392 B

    cudaFuncSetAttribute(cswin_fused,
                         cudaFuncAttributeMaxDynamicSharedMemorySize, SMEM);
    cswin_fused<<<256, 512, SMEM>>>(q, k, v, cw, out);
}